// round 16
// baseline (speedup 1.0000x reference)
#include <cuda_runtime.h>
#include <cuda_fp16.h>
#include <cstdint>

#define B_  64
#define NI  2048
#define DI  16
#define NO  32
#define DO  32
#define CH  16            // i-chunks per (b) for round partials
#define IC  (NI / CH)     // 128 i per chunk

// u_hat layout: [b][i][od(1024)] fp16, 268 MB
__device__ __half g_uhat[(size_t)B_ * NI * NO * DO];
__device__ float  g_partA[B_ * CH * NO * DO];   // round0 partials
__device__ float  g_partB[B_ * CH * NO * DO];   // round1 partials
__device__ float  g_partC[B_ * CH * NO * DO];   // round2 partials

// ---------- packed f32x2 helpers ----------
__device__ __forceinline__ unsigned long long splat2(float v) {
    unsigned long long r;
    asm("mov.b64 %0, {%1, %1};" : "=l"(r) : "f"(v));
    return r;
}
__device__ __forceinline__ void ffma2(unsigned long long &d,
                                      unsigned long long a, unsigned long long b) {
    asm("fma.rn.f32x2 %0, %1, %2, %0;" : "+l"(d) : "l"(a), "l"(b));
}
__device__ __forceinline__ float2 unpack2(unsigned long long v) {
    float2 f;
    asm("mov.b64 {%0, %1}, %2;" : "=f"(f.x), "=f"(f.y) : "l"(v));
    return f;
}

// ---------------------------------------------------------------------------
// K1 (verbatim champion): 256 threads, 2 CTAs/SM, oo-loop reusing W regs.
// ---------------------------------------------------------------------------
__global__ __launch_bounds__(256, 2)
void k1_uhat(const float* __restrict__ x, const float* __restrict__ W) {
    const int i = blockIdx.x;
    const int t = threadIdx.x;

    __shared__ __align__(16) float xs[DI][B_];
    {
        int idx = t;
        #pragma unroll
        for (int r = 0; r < 4; r++, idx += 256) {
            int b = idx >> 4, k = idx & 15;
            xs[k][b] = x[((size_t)b * NI + i) * DI + k];
        }
    }
    __syncthreads();

    const int o_lo = t >> 4, dp = t & 15;        // d = 2dp, 2dp+1
    const size_t bs2 = (size_t)NI * 512;         // half2 stride per b

    #pragma unroll 1
    for (int oo = 0; oo < 2; oo++) {
        const int o = o_lo + oo * 16;

        const float4* wp = reinterpret_cast<const float4*>(W) +
                           ((((size_t)o * NI + i) * DO + 2 * dp) * DI >> 2);
        float4 qa = wp[0], qb = wp[1], qc = wp[2], qd = wp[3];
        float4 qe = wp[4], qf = wp[5], qg = wp[6], qh = wp[7];

        unsigned long long w0[16], w1[16];
        w0[0]=splat2(qa.x); w0[1]=splat2(qa.y); w0[2]=splat2(qa.z); w0[3]=splat2(qa.w);
        w0[4]=splat2(qb.x); w0[5]=splat2(qb.y); w0[6]=splat2(qb.z); w0[7]=splat2(qb.w);
        w0[8]=splat2(qc.x); w0[9]=splat2(qc.y); w0[10]=splat2(qc.z); w0[11]=splat2(qc.w);
        w0[12]=splat2(qd.x); w0[13]=splat2(qd.y); w0[14]=splat2(qd.z); w0[15]=splat2(qd.w);
        w1[0]=splat2(qe.x); w1[1]=splat2(qe.y); w1[2]=splat2(qe.z); w1[3]=splat2(qe.w);
        w1[4]=splat2(qf.x); w1[5]=splat2(qf.y); w1[6]=splat2(qf.z); w1[7]=splat2(qf.w);
        w1[8]=splat2(qg.x); w1[9]=splat2(qg.y); w1[10]=splat2(qg.z); w1[11]=splat2(qg.w);
        w1[12]=splat2(qh.x); w1[13]=splat2(qh.y); w1[14]=splat2(qh.z); w1[15]=splat2(qh.w);

        __half2* ob = reinterpret_cast<__half2*>(g_uhat) +
                      (size_t)i * 512 + o * 16 + dp;

        #pragma unroll 1
        for (int bq = 0; bq < 16; bq++) {
            const int b = bq * 4;
            unsigned long long a0p = 0ull, a0q = 0ull;
            unsigned long long a1p = 0ull, a1q = 0ull;
            #pragma unroll
            for (int k = 0; k < 16; k++) {
                ulonglong2 xq = *reinterpret_cast<const ulonglong2*>(&xs[k][b]);
                ffma2(a0p, w0[k], xq.x);
                ffma2(a0q, w0[k], xq.y);
                ffma2(a1p, w1[k], xq.x);
                ffma2(a1q, w1[k], xq.y);
            }
            float2 f0p = unpack2(a0p), f0q = unpack2(a0q);
            float2 f1p = unpack2(a1p), f1q = unpack2(a1q);
            ob[(size_t)(b + 0) * bs2] = __float22half2_rn(make_float2(f0p.x, f1p.x));
            ob[(size_t)(b + 1) * bs2] = __float22half2_rn(make_float2(f0p.y, f1p.y));
            ob[(size_t)(b + 2) * bs2] = __float22half2_rn(make_float2(f0q.x, f1q.x));
            ob[(size_t)(b + 3) * bs2] = __float22half2_rn(make_float2(f0q.y, f1q.y));
        }
    }
}

// ---------------------------------------------------------------------------
// Routing round, fused vsum prologue + exp hoisted into phase A.
// CTA = (chunk, b), 256 threads. Warp covers 8 o x 4 q (q owns 8 d).
// mode 0: c=1/32 -> pA.  mode 1: v(pA) -> pB.  mode 2: v(pA)+v(pB) -> pC.
// ---------------------------------------------------------------------------
__global__ __launch_bounds__(256)
void k_round(int mode) {
    const int ch = blockIdx.x, b = blockIdx.y;
    const int t = threadIdx.x;
    const int w = t >> 5, lane = t & 31;
    const int o = ((w & 3) << 3) + (lane >> 2);
    const int q = lane & 3;
    const int half = w >> 2;

    // ---- fused vsum prologue (order matches stage2 exactly)
    float vs[8];
    if (mode >= 1) {
        #pragma unroll
        for (int d = 0; d < 8; d++) vs[d] = 0.f;
        const float* bufs[2] = { g_partA, g_partB };
        const int nbuf = (mode == 2) ? 2 : 1;
        for (int bi = 0; bi < nbuf; bi++) {
            float s0[8];
            #pragma unroll
            for (int d = 0; d < 8; d++) s0[d] = 0.f;
            const float4* pp = reinterpret_cast<const float4*>(
                bufs[bi] + (size_t)(b * CH) * (NO * DO) + o * DO + q * 8);
            #pragma unroll
            for (int c = 0; c < CH; c++) {
                float4 x0 = pp[c * (NO * DO / 4)];
                float4 x1 = pp[c * (NO * DO / 4) + 1];
                s0[0]+=x0.x; s0[1]+=x0.y; s0[2]+=x0.z; s0[3]+=x0.w;
                s0[4]+=x1.x; s0[5]+=x1.y; s0[6]+=x1.z; s0[7]+=x1.w;
            }
            float nrm = 0.f;
            #pragma unroll
            for (int d = 0; d < 8; d++) nrm += s0[d] * s0[d];
            nrm += __shfl_xor_sync(0xffffffffu, nrm, 1);
            nrm += __shfl_xor_sync(0xffffffffu, nrm, 2);   // ||s||^2 over 32 d
            float scale = nrm / (1.0f + nrm) * rsqrtf(nrm + 1e-7f);
            #pragma unroll
            for (int d = 0; d < 8; d++) vs[d] += s0[d] * scale;
        }
    }

    float sp[8];
    #pragma unroll
    for (int d = 0; d < 8; d++) sp[d] = 0.f;

    __shared__ float s_e[8][NO];    // exp(logit), written in phase A
    __shared__ float s_c[8][NO];

    const uint4* up = reinterpret_cast<const uint4*>(g_uhat) +
                      ((size_t)b * NI + (size_t)ch * IC) * 128 + o * 4 + q;

    #pragma unroll 1
    for (int ib = 0; ib < IC; ib += 8) {
        uint4 raw[4];
        #pragma unroll
        for (int v = 0; v < 4; v++)
            raw[v] = up[(size_t)(ib + half * 4 + v) * 128];

        float F[4][8];
        #pragma unroll
        for (int v = 0; v < 4; v++) {
            float2 fa = __half22float2(*reinterpret_cast<__half2*>(&raw[v].x));
            float2 fb = __half22float2(*reinterpret_cast<__half2*>(&raw[v].y));
            float2 fc = __half22float2(*reinterpret_cast<__half2*>(&raw[v].z));
            float2 fd = __half22float2(*reinterpret_cast<__half2*>(&raw[v].w));
            F[v][0]=fa.x; F[v][1]=fa.y; F[v][2]=fb.x; F[v][3]=fb.y;
            F[v][4]=fc.x; F[v][5]=fc.y; F[v][6]=fd.x; F[v][7]=fd.y;
        }

        if (mode >= 1) {
            // phase A: db = vsum . u_hat; exp computed pre-barrier (q==0)
            #pragma unroll
            for (int v = 0; v < 4; v++) {
                float tdb = F[v][0]*vs[0] + F[v][1]*vs[1] + F[v][2]*vs[2] +
                            F[v][3]*vs[3] + F[v][4]*vs[4] + F[v][5]*vs[5] +
                            F[v][6]*vs[6] + F[v][7]*vs[7];
                tdb += __shfl_xor_sync(0xffffffffu, tdb, 2);
                tdb += __shfl_xor_sync(0xffffffffu, tdb, 1);
                if (q == 0) s_e[half * 4 + v][o] = __expf(tdb);
            }
            __syncthreads();
            // phase B: normalize (sum + fast div only; exp already done)
            {
                float e = s_e[w][lane];
                float sm = e;
                #pragma unroll
                for (int st = 16; st; st >>= 1)
                    sm += __shfl_xor_sync(0xffffffffu, sm, st);
                s_c[w][lane] = __fdividef(e, sm);
            }
            __syncthreads();
            // phase C: s += c * u_hat
            #pragma unroll
            for (int v = 0; v < 4; v++) {
                float c = s_c[half * 4 + v][o];
                #pragma unroll
                for (int d = 0; d < 8; d++) sp[d] += c * F[v][d];
            }
        } else {
            #pragma unroll
            for (int v = 0; v < 4; v++)
                #pragma unroll
                for (int d = 0; d < 8; d++) sp[d] += F[v][d];
        }
    }

    if (mode == 0) {
        const float c = 1.0f / (float)NO;
        #pragma unroll
        for (int d = 0; d < 8; d++) sp[d] *= c;
    }

    __shared__ float s_red[256 * 8];
    #pragma unroll
    for (int d = 0; d < 8; d++)
        s_red[(t & 127) * 8 + d + (half ? 1024 : 0)] = sp[d];
    __syncthreads();
    if (half == 0) {
        float* wb = (mode == 0) ? g_partA : (mode == 1 ? g_partB : g_partC);
        float4* pp = reinterpret_cast<float4*>(
            wb + ((b * CH + ch) * (NO * DO)) + o * DO + q * 8);
        float4 r0, r1;
        int base = (t & 127) * 8;
        r0.x = s_red[base+0] + s_red[base+0+1024];
        r0.y = s_red[base+1] + s_red[base+1+1024];
        r0.z = s_red[base+2] + s_red[base+2+1024];
        r0.w = s_red[base+3] + s_red[base+3+1024];
        r1.x = s_red[base+4] + s_red[base+4+1024];
        r1.y = s_red[base+5] + s_red[base+5+1024];
        r1.z = s_red[base+6] + s_red[base+6+1024];
        r1.w = s_red[base+7] + s_red[base+7+1024];
        pp[0] = r0; pp[1] = r1;
    }
}

// ---------------------------------------------------------------------------
// Final: reduce round-2 partials -> s, squash -> v, write output.
// ---------------------------------------------------------------------------
__global__ __launch_bounds__(1024)
void k_fin(float* __restrict__ out) {
    const int b = blockIdx.x, t = threadIdx.x;
    float s = 0.f;
    #pragma unroll
    for (int c = 0; c < CH; c++)
        s += g_partC[(b * CH + c) * (NO * DO) + t];

    float sq = s * s;
    #pragma unroll
    for (int st = 16; st; st >>= 1)
        sq += __shfl_xor_sync(0xffffffffu, sq, st);

    float scale = sq / (1.0f + sq) * rsqrtf(sq + 1e-7f);
    out[b * (NO * DO) + t] = s * scale;
}

// ---------------------------------------------------------------------------
extern "C" void kernel_launch(void* const* d_in, const int* in_sizes, int n_in,
                              void* d_out, int out_size) {
    const float* x = (const float*)d_in[0];
    const float* W = (const float*)d_in[1];
    if (in_sizes[0] != B_ * NI * DI) {
        x = (const float*)d_in[1];
        W = (const float*)d_in[0];
    }
    float* out = (float*)d_out;

    k1_uhat<<<NI, 256>>>(x, W);

    dim3 rg(CH, B_);
    k_round<<<rg, 256>>>(0);
    k_round<<<rg, 256>>>(1);
    k_round<<<rg, 256>>>(2);
    k_fin<<<B_, NO * DO>>>(out);
}

// round 17
// speedup vs baseline: 1.0882x; 1.0882x over previous
#include <cuda_runtime.h>
#include <cuda_fp16.h>
#include <cstdint>

#define B_  64
#define NI  2048
#define DI  16
#define NO  32
#define DO  32
#define CH  16            // i-chunks per (b) for round partials
#define IC  (NI / CH)     // 128 i per chunk

// u_hat layout: [b][i][od(1024)] fp16, 268 MB
__device__ __half g_uhat[(size_t)B_ * NI * NO * DO];
__device__ float  g_part[B_ * CH * NO * DO];
__device__ float  g_vsum[B_ * NO * DO];

// ---------- packed f32x2 helpers ----------
__device__ __forceinline__ unsigned long long splat2(float v) {
    unsigned long long r;
    asm("mov.b64 %0, {%1, %1};" : "=l"(r) : "f"(v));
    return r;
}
__device__ __forceinline__ void ffma2(unsigned long long &d,
                                      unsigned long long a, unsigned long long b) {
    asm("fma.rn.f32x2 %0, %1, %2, %0;" : "+l"(d) : "l"(a), "l"(b));
}
__device__ __forceinline__ float2 unpack2(unsigned long long v) {
    float2 f;
    asm("mov.b64 {%0, %1}, %2;" : "=f"(f.x), "=f"(f.y) : "l"(v));
    return f;
}

// ---------------------------------------------------------------------------
// K1 (verbatim champion): 256 threads, 2 CTAs/SM, oo-loop reusing W regs.
// u_hat[b][i][od] = sum_k W[o][i][d][k] * x[b][i][k]   (fp16 out)
// ---------------------------------------------------------------------------
__global__ __launch_bounds__(256, 2)
void k1_uhat(const float* __restrict__ x, const float* __restrict__ W) {
    const int i = blockIdx.x;
    const int t = threadIdx.x;

    __shared__ __align__(16) float xs[DI][B_];
    {
        int idx = t;
        #pragma unroll
        for (int r = 0; r < 4; r++, idx += 256) {
            int b = idx >> 4, k = idx & 15;
            xs[k][b] = x[((size_t)b * NI + i) * DI + k];
        }
    }
    __syncthreads();

    const int o_lo = t >> 4, dp = t & 15;        // d = 2dp, 2dp+1
    const size_t bs2 = (size_t)NI * 512;         // half2 stride per b

    #pragma unroll 1
    for (int oo = 0; oo < 2; oo++) {
        const int o = o_lo + oo * 16;

        const float4* wp = reinterpret_cast<const float4*>(W) +
                           ((((size_t)o * NI + i) * DO + 2 * dp) * DI >> 2);
        float4 qa = wp[0], qb = wp[1], qc = wp[2], qd = wp[3];
        float4 qe = wp[4], qf = wp[5], qg = wp[6], qh = wp[7];

        unsigned long long w0[16], w1[16];
        w0[0]=splat2(qa.x); w0[1]=splat2(qa.y); w0[2]=splat2(qa.z); w0[3]=splat2(qa.w);
        w0[4]=splat2(qb.x); w0[5]=splat2(qb.y); w0[6]=splat2(qb.z); w0[7]=splat2(qb.w);
        w0[8]=splat2(qc.x); w0[9]=splat2(qc.y); w0[10]=splat2(qc.z); w0[11]=splat2(qc.w);
        w0[12]=splat2(qd.x); w0[13]=splat2(qd.y); w0[14]=splat2(qd.z); w0[15]=splat2(qd.w);
        w1[0]=splat2(qe.x); w1[1]=splat2(qe.y); w1[2]=splat2(qe.z); w1[3]=splat2(qe.w);
        w1[4]=splat2(qf.x); w1[5]=splat2(qf.y); w1[6]=splat2(qf.z); w1[7]=splat2(qf.w);
        w1[8]=splat2(qg.x); w1[9]=splat2(qg.y); w1[10]=splat2(qg.z); w1[11]=splat2(qg.w);
        w1[12]=splat2(qh.x); w1[13]=splat2(qh.y); w1[14]=splat2(qh.z); w1[15]=splat2(qh.w);

        __half2* ob = reinterpret_cast<__half2*>(g_uhat) +
                      (size_t)i * 512 + o * 16 + dp;

        #pragma unroll 1
        for (int bq = 0; bq < 16; bq++) {
            const int b = bq * 4;
            unsigned long long a0p = 0ull, a0q = 0ull;
            unsigned long long a1p = 0ull, a1q = 0ull;
            #pragma unroll
            for (int k = 0; k < 16; k++) {
                ulonglong2 xq = *reinterpret_cast<const ulonglong2*>(&xs[k][b]);
                ffma2(a0p, w0[k], xq.x);
                ffma2(a0q, w0[k], xq.y);
                ffma2(a1p, w1[k], xq.x);
                ffma2(a1q, w1[k], xq.y);
            }
            float2 f0p = unpack2(a0p), f0q = unpack2(a0q);
            float2 f1p = unpack2(a1p), f1q = unpack2(a1q);
            ob[(size_t)(b + 0) * bs2] = __float22half2_rn(make_float2(f0p.x, f1p.x));
            ob[(size_t)(b + 1) * bs2] = __float22half2_rn(make_float2(f0p.y, f1p.y));
            ob[(size_t)(b + 2) * bs2] = __float22half2_rn(make_float2(f0q.x, f1q.x));
            ob[(size_t)(b + 3) * bs2] = __float22half2_rn(make_float2(f0q.y, f1q.y));
        }
    }
}

// ---------------------------------------------------------------------------
// Routing round (R15 structure; phase B post-barrier chain trimmed further:
// exp hoisted pre-barrier into phase A, and the 32-value sum done as
// LDS.128 + 3 adds + 3 shfl instead of 5 shfl).
// CTA = (chunk, b), 256 threads.
// ---------------------------------------------------------------------------
__global__ __launch_bounds__(256)
void k_round(int use_vsum) {
    const int ch = blockIdx.x, b = blockIdx.y;
    const int t = threadIdx.x;
    const int w = t >> 5, lane = t & 31;
    const int o = ((w & 3) << 3) + (lane >> 2);
    const int q = lane & 3;
    const int half = w >> 2;

    float vs[8];
    if (use_vsum) {
        const float4* vp = reinterpret_cast<const float4*>(
            g_vsum + (b * NO + o) * DO + q * 8);
        float4 va = vp[0], vb = vp[1];
        vs[0]=va.x; vs[1]=va.y; vs[2]=va.z; vs[3]=va.w;
        vs[4]=vb.x; vs[5]=vb.y; vs[6]=vb.z; vs[7]=vb.w;
    }

    float sp[8];
    #pragma unroll
    for (int d = 0; d < 8; d++) sp[d] = 0.f;

    __shared__ __align__(16) float s_e[8][NO];   // exp(logit), phase-A written
    __shared__ float s_c[8][NO];

    const uint4* up = reinterpret_cast<const uint4*>(g_uhat) +
                      ((size_t)b * NI + (size_t)ch * IC) * 128 + o * 4 + q;

    #pragma unroll 1
    for (int ib = 0; ib < IC; ib += 8) {
        uint4 raw[4];
        #pragma unroll
        for (int v = 0; v < 4; v++)
            raw[v] = up[(size_t)(ib + half * 4 + v) * 128];

        float F[4][8];
        #pragma unroll
        for (int v = 0; v < 4; v++) {
            float2 fa = __half22float2(*reinterpret_cast<__half2*>(&raw[v].x));
            float2 fb = __half22float2(*reinterpret_cast<__half2*>(&raw[v].y));
            float2 fc = __half22float2(*reinterpret_cast<__half2*>(&raw[v].z));
            float2 fd = __half22float2(*reinterpret_cast<__half2*>(&raw[v].w));
            F[v][0]=fa.x; F[v][1]=fa.y; F[v][2]=fb.x; F[v][3]=fb.y;
            F[v][4]=fc.x; F[v][5]=fc.y; F[v][6]=fd.x; F[v][7]=fd.y;
        }

        if (use_vsum) {
            // phase A: db = vsum . u_hat; exp computed PRE-barrier (q==0)
            #pragma unroll
            for (int v = 0; v < 4; v++) {
                float tdb = F[v][0]*vs[0] + F[v][1]*vs[1] + F[v][2]*vs[2] +
                            F[v][3]*vs[3] + F[v][4]*vs[4] + F[v][5]*vs[5] +
                            F[v][6]*vs[6] + F[v][7]*vs[7];
                tdb += __shfl_xor_sync(0xffffffffu, tdb, 2);
                tdb += __shfl_xor_sync(0xffffffffu, tdb, 1);
                if (q == 0) s_e[half * 4 + v][o] = __expf(tdb);
            }
            __syncthreads();
            // phase B: normalize. Row sum via LDS.128 + 3 adds + 3 shfl.
            // Lanes l, l+8, l+16, l+24 read the same chunk (smem broadcast);
            // after xor 1,2,4 every lane holds the full 32-value sum.
            {
                const float4* row4 = reinterpret_cast<const float4*>(&s_e[w][0]);
                float4 c4 = row4[lane & 7];
                float ps = (c4.x + c4.y) + (c4.z + c4.w);
                ps += __shfl_xor_sync(0xffffffffu, ps, 1);
                ps += __shfl_xor_sync(0xffffffffu, ps, 2);
                ps += __shfl_xor_sync(0xffffffffu, ps, 4);
                float e = s_e[w][lane];
                s_c[w][lane] = __fdividef(e, ps);
            }
            __syncthreads();
            // phase C: s += c * u_hat
            #pragma unroll
            for (int v = 0; v < 4; v++) {
                float c = s_c[half * 4 + v][o];
                #pragma unroll
                for (int d = 0; d < 8; d++) sp[d] += c * F[v][d];
            }
        } else {
            #pragma unroll
            for (int v = 0; v < 4; v++)
                #pragma unroll
                for (int d = 0; d < 8; d++) sp[d] += F[v][d];
        }
    }

    if (!use_vsum) {
        const float c = 1.0f / (float)NO;
        #pragma unroll
        for (int d = 0; d < 8; d++) sp[d] *= c;
    }

    __shared__ float s_red[256 * 8];
    #pragma unroll
    for (int d = 0; d < 8; d++)
        s_red[(t & 127) * 8 + d + (half ? 1024 : 0)] = sp[d];
    __syncthreads();
    if (half == 0) {
        float4* pp = reinterpret_cast<float4*>(
            g_part + ((b * CH + ch) * (NO * DO)) + o * DO + q * 8);
        float4 r0, r1;
        int base = (t & 127) * 8;
        r0.x = s_red[base+0] + s_red[base+0+1024];
        r0.y = s_red[base+1] + s_red[base+1+1024];
        r0.z = s_red[base+2] + s_red[base+2+1024];
        r0.w = s_red[base+3] + s_red[base+3+1024];
        r1.x = s_red[base+4] + s_red[base+4+1024];
        r1.y = s_red[base+5] + s_red[base+5+1024];
        r1.z = s_red[base+6] + s_red[base+6+1024];
        r1.w = s_red[base+7] + s_red[base+7+1024];
        pp[0] = r0; pp[1] = r1;
    }
}

// ---------------------------------------------------------------------------
// Stage 2 (verbatim): reduce partials -> s, squash -> v, update vsum / out.
// ---------------------------------------------------------------------------
__global__ __launch_bounds__(1024)
void k_stage2(float* __restrict__ out, int round) {
    const int b = blockIdx.x, t = threadIdx.x;
    float s = 0.f;
    #pragma unroll
    for (int c = 0; c < CH; c++)
        s += g_part[(b * CH + c) * (NO * DO) + t];

    float sq = s * s;
    #pragma unroll
    for (int st = 16; st; st >>= 1)
        sq += __shfl_xor_sync(0xffffffffu, sq, st);

    float scale = sq / (1.0f + sq) * rsqrtf(sq + 1e-7f);
    float v = s * scale;

    int idx = b * (NO * DO) + t;
    if (round == 2)      out[idx] = v;
    else if (round == 0) g_vsum[idx] = v;
    else                 g_vsum[idx] += v;
}

// ---------------------------------------------------------------------------
extern "C" void kernel_launch(void* const* d_in, const int* in_sizes, int n_in,
                              void* d_out, int out_size) {
    const float* x = (const float*)d_in[0];
    const float* W = (const float*)d_in[1];
    if (in_sizes[0] != B_ * NI * DI) {
        x = (const float*)d_in[1];
        W = (const float*)d_in[0];
    }
    float* out = (float*)d_out;

    k1_uhat<<<NI, 256>>>(x, W);

    dim3 rg(CH, B_);
    k_round<<<rg, 256>>>(0);
    k_stage2<<<B_, NO * DO>>>(out, 0);
    k_round<<<rg, 256>>>(1);
    k_stage2<<<B_, NO * DO>>>(out, 1);
    k_round<<<rg, 256>>>(2);
    k_stage2<<<B_, NO * DO>>>(out, 2);
}